// round 15
// baseline (speedup 1.0000x reference)
#include <cuda_runtime.h>
#include <cuda.h>
#include <cuda_fp16.h>
#include <math.h>
#include <stdint.h>

// Problem dims (fixed by setup_inputs)
#define T_TOK 2048
#define DIM   2048
#define NEXP  16
#define IDIM  1024
#define SIDIM 2048
#define TOPK  4

#define BM 128
#define MAXROWS (T_TOK*TOPK + NEXP*BM)   // 10240
#define MAXTILES (MAXROWS/BM)            // 80

// ======================= scratch (device globals) =======================
__device__ __half g_x16[(size_t)T_TOK*DIM];         // x fp16
__device__ __half g_zero[DIM];                      // zero row (static zero-init)
__device__ __half g_wguT[(size_t)NEXP*2*IDIM*DIM];  // pair-interleaved gate/up rows
__device__ __half g_wdT[(size_t)NEXP*DIM*IDIM];
__device__ __half g_wsguT[(size_t)2*SIDIM*DIM];     // pair-interleaved
__device__ __half g_wsdT[(size_t)DIM*SIDIM];
__device__ __half g_hb[(size_t)MAXROWS*IDIM];       // routed hidden fp16
__device__ __half g_hsh[(size_t)T_TOK*SIDIM];       // shared hidden fp16
__device__ float g_eout[(size_t)MAXROWS*DIM];

__device__ int   g_topidx[T_TOK*TOPK];
__device__ float g_topw[T_TOK*TOPK];
__device__ int   g_counts[NEXP];
__device__ int   g_fill[NEXP];
__device__ int   g_offsets[NEXP];
__device__ int   g_tile_expert[MAXTILES];
__device__ int   g_rowtok[MAXROWS];
__device__ int   g_posmap[T_TOK*TOPK];

__device__ __forceinline__ float4 ld4(const float* p) {
    return *reinterpret_cast<const float4*>(p);
}

__device__ __forceinline__ uint32_t smem_to_u32(const void* smem_ptr) {
    uint32_t addr;
    asm("{ .reg .u64 tmp; cvta.to.shared.u64 tmp, %1; cvt.u32.u64 %0, tmp; }"
        : "=r"(addr) : "l"(smem_ptr));
    return addr;
}

// ======================= router (+ fused x fp32->fp16) =======================
__global__ void router_kernel(const float* __restrict__ x,
                              const float* __restrict__ gw,
                              const float* __restrict__ gb,
                              __half* __restrict__ x16)
{
    __shared__ float sx[DIM];
    __shared__ float slog[NEXP];
    const int t   = blockIdx.x;
    const int tid = threadIdx.x;           // 512 threads

    float4 xv0 = ld4(x + (long long)t*DIM + tid*4);
    *reinterpret_cast<float4*>(&sx[tid*4]) = xv0;
    {
        union { __half b[4]; unsigned long long u; } H;
        H.b[0] = __float2half(xv0.x); H.b[1] = __float2half(xv0.y);
        H.b[2] = __float2half(xv0.z); H.b[3] = __float2half(xv0.w);
        *reinterpret_cast<unsigned long long*>(x16 + (long long)t*DIM + tid*4) = H.u;
    }
    __syncthreads();

    const int w = tid >> 5, lane = tid & 31;
    const float* gwr = gw + w*DIM;
    float s = 0.f;
    for (int i = lane*4; i < DIM; i += 32*4) {
        float4 xv = *reinterpret_cast<float4*>(&sx[i]);
        float4 gv = ld4(gwr + i);
        s += xv.x*gv.x + xv.y*gv.y + xv.z*gv.z + xv.w*gv.w;
    }
    #pragma unroll
    for (int o = 16; o; o >>= 1) s += __shfl_down_sync(0xffffffffu, s, o);
    if (lane == 0) slog[w] = s;
    __syncthreads();

    if (tid == 0) {
        float p[NEXP], mx = -1e30f;
        #pragma unroll
        for (int e = 0; e < NEXP; e++) mx = fmaxf(mx, slog[e]);
        float sum = 0.f;
        #pragma unroll
        for (int e = 0; e < NEXP; e++) { p[e] = expf(slog[e] - mx); sum += p[e]; }
        const float inv = 1.f / sum;
        float score[NEXP];
        #pragma unroll
        for (int e = 0; e < NEXP; e++) { p[e] *= inv; score[e] = p[e] + gb[e]; }

        int sel[TOPK]; float wsum = 0.f;
        #pragma unroll
        for (int k = 0; k < TOPK; k++) {
            int best = 0; float bv = -1e30f;
            #pragma unroll
            for (int e = 0; e < NEXP; e++)
                if (score[e] > bv) { bv = score[e]; best = e; }
            sel[k] = best; score[best] = -1e31f; wsum += p[best];
        }
        const float invw = 1.f / wsum;
        #pragma unroll
        for (int k = 0; k < TOPK; k++) {
            g_topidx[t*TOPK + k] = sel[k];
            g_topw [t*TOPK + k] = p[sel[k]] * invw;
            atomicAdd(&g_counts[sel[k]], 1);
        }
    }
}

__global__ void zero_meta()
{
    int i = threadIdx.x;
    if (i < NEXP) { g_counts[i] = 0; g_fill[i] = 0; }
}

__global__ void sched_kernel()
{
    const int tid = threadIdx.x;
    if (tid == 0) {
        int base = 0;
        for (int e = 0; e < NEXP; e++) {
            g_offsets[e] = base;
            int nt = (g_counts[e] + BM - 1) / BM;
            int t0 = base / BM;
            for (int j = 0; j < nt; j++) g_tile_expert[t0 + j] = e;
            base += nt * BM;
        }
        for (int tl = base / BM; tl < MAXTILES; tl++) g_tile_expert[tl] = -1;
    }
    for (int i = tid; i < MAXROWS; i += blockDim.x) g_rowtok[i] = -1;
}

__global__ void scatter_kernel()
{
    const int p = blockIdx.x * blockDim.x + threadIdx.x;
    if (p >= T_TOK*TOPK) return;
    const int e = g_topidx[p];
    const int r = atomicAdd(&g_fill[e], 1);
    const int pos = g_offsets[e] + r;
    g_rowtok[pos] = p >> 2;
    g_posmap[p]   = pos;
}

// ======================= weight conversion =======================
// fp32 src [E][R][C] -> fp16 dst [E][C][R]  (transpose + convert)
// glu_half H != 0: pair-interleave at 8-col granularity —
//   gate col c  -> row (c>>3)*16 + (c&7)
//   up   col c' -> row (c'>>3)*16 + 8 + (c'&7)
// so each n8 mma block pair (even=gate, odd=up) covers the SAME 8 h-columns.
__global__ void transpose_convert(const float* __restrict__ src,
                                  __half* __restrict__ dst,
                                  int R, int C, int glu_half)
{
    __shared__ float t[32][33];
    const int e  = blockIdx.z;
    const int c0 = blockIdx.x * 32;
    const int r0 = blockIdx.y * 32;
    const int tx = threadIdx.x, ty = threadIdx.y;   // (32, 8)
    const float* s = src + (long long)e*R*C;
    #pragma unroll
    for (int j = 0; j < 32; j += 8)
        t[ty+j][tx] = s[(long long)(r0+ty+j)*C + c0+tx];
    __syncthreads();
    __half* o = dst + (long long)e*C*R;
    #pragma unroll
    for (int j = 0; j < 32; j += 8) {
        float v = t[tx][ty+j];
        int c = c0 + ty + j;
        long long dr;
        if (glu_half == 0) dr = c;
        else if (c < glu_half) dr = (long long)(c >> 3)*16 + (c & 7);
        else { int cc = c - glu_half; dr = (long long)(cc >> 3)*16 + 8 + (cc & 7); }
        o[dr*R + r0+tx] = __float2half(v);
    }
}

// ======================= mma.sync GEMM core (fp16, 128x256 tile) =======================
// A [128,K] via per-thread row ptr, B [256 rows, K] fp16 K-contig. fp32 accum.
// 256 threads = 8 warps (2 M x 4 N); warp tile 64x64; mma m16n8k16; k-step 16.
// Stage = A 4KB + B 8KB = 12KB (32B rows, swizzle c^((r>>2)&1)); 4 stages = 48KB.

#define SWZB(r, c)  ((uint32_t)(r)*32u + ((uint32_t)(((c) ^ (((r)>>2)&1))) << 4))
#define B_OFF 4096
#define STG   12288

__device__ __forceinline__ void cp16(uint32_t d, const void* s) {
    asm volatile("cp.async.cg.shared.global [%0], [%1], 16;\n" :: "r"(d), "l"(s));
}
__device__ __forceinline__ void ldm4(uint32_t* r, uint32_t a) {
    asm volatile("ldmatrix.sync.aligned.m8n8.x4.shared.b16 {%0,%1,%2,%3}, [%4];\n"
        : "=r"(r[0]), "=r"(r[1]), "=r"(r[2]), "=r"(r[3]) : "r"(a));
}
__device__ __forceinline__ void mma16816(float* c, const uint32_t* a, uint32_t b0, uint32_t b1) {
    asm volatile("mma.sync.aligned.m16n8k16.row.col.f32.f16.f16.f32 "
        "{%0,%1,%2,%3}, {%4,%5,%6,%7}, {%8,%9}, {%0,%1,%2,%3};\n"
        : "+f"(c[0]), "+f"(c[1]), "+f"(c[2]), "+f"(c[3])
        : "r"(a[0]), "r"(a[1]), "r"(a[2]), "r"(a[3]), "r"(b0), "r"(b1));
}

// aptr: A row (tid>>1) base; bptr: B row (tid) base
__device__ __forceinline__ void load_stage(uint32_t st,
    const __half* __restrict__ aptr, const __half* __restrict__ bptr,
    int k0, int tid)
{
    const int arow = tid >> 1;
    const int acb  = tid & 1;
    cp16(st +         SWZB(arow, acb), aptr + k0 + acb*8);
    cp16(st + B_OFF + SWZB(tid, 0),    bptr + k0);
    cp16(st + B_OFF + SWZB(tid, 1),    bptr + k0 + 8);
}

__device__ __forceinline__ void gemm_mainloop(uint32_t sb,
    const __half* __restrict__ aptr, const __half* __restrict__ bptr,
    int K, int tid, int lane, int wm, int wn,
    float acc[4][8][4])
{
    const int nk = K / 16;

    load_stage(sb,         aptr, bptr, 0,  tid);
    asm volatile("cp.async.commit_group;\n");
    load_stage(sb + STG,   aptr, bptr, 16, tid);
    asm volatile("cp.async.commit_group;\n");
    load_stage(sb + 2*STG, aptr, bptr, 32, tid);
    asm volatile("cp.async.commit_group;\n");

    for (int kt = 0; kt < nk; kt++) {
        asm volatile("cp.async.wait_group 2;\n");
        __syncthreads();

        if (kt + 3 < nk)
            load_stage(sb + ((kt+3)&3)*STG, aptr, bptr, (kt+3)*16, tid);
        asm volatile("cp.async.commit_group;\n");

        const uint32_t Ab = sb + (kt & 3)*STG;

        // B fragments: 4 x n16k16 per warp (64 columns)
        uint32_t fb[4][4];
        #pragma unroll
        for (int np = 0; np < 4; np++) {
            const int rb = wn*64 + np*16 + (lane & 7) + ((lane >> 4) << 3);
            const int cb = (lane >> 3) & 1;
            ldm4(fb[np], Ab + B_OFF + SWZB(rb, cb));
        }

        #pragma unroll
        for (int mt = 0; mt < 4; mt++) {
            uint32_t fa[4];
            const int ra = wm*64 + mt*16 + (lane & 15);
            const int ca = lane >> 4;
            ldm4(fa, Ab + SWZB(ra, ca));
            #pragma unroll
            for (int nt = 0; nt < 8; nt++) {
                const int np = nt >> 1, hx = (nt & 1)*2;
                mma16816(acc[mt][nt], fa, fb[np][hx], fb[np][hx+1]);
            }
        }
    }
    asm volatile("cp.async.wait_group 0;\n");
}

// ---------- merged gate_up GEMM, fused gather + register-local SwiGLU ----------
// grid.x = 896: [0,640) routed (8 x-tiles, 80 y), [640,896) shared (16 x, 16 y)
// B pair-interleaved: n8 block 2q = gate, 2q+1 = up for the SAME 8 h-cols.
__global__ void __launch_bounds__(256, 1) gemm_gu_fused(
    const __half* __restrict__ x16, const __half* __restrict__ B_r,
    __half* __restrict__ C_r,
    const __half* __restrict__ B_s, __half* __restrict__ C_s,
    const int* __restrict__ tile_expert)
{
    __shared__ char smem[4*STG];   // 49152
    const uint32_t sb = smem_to_u32(smem);

    const int tid = threadIdx.x, lane = tid & 31, wid = tid >> 5;
    const int wm = wid & 1, wn = wid >> 1;

    const __half *aptr, *bptr;
    __half *C;
    int m0, ldh, hcol0;
    int bid = blockIdx.x;
    if (bid < 640) {
        const int bx = bid & 7, by = bid >> 3;
        const int e = tile_expert[by];
        if (e < 0) return;
        m0 = by*128; hcol0 = bx*128;
        const int tok = g_rowtok[m0 + (tid >> 1)];
        aptr = (tok >= 0) ? (x16 + (size_t)tok*DIM) : g_zero;
        bptr = B_r + (size_t)(e*(2*IDIM) + bx*256 + tid)*DIM;
        C = C_r; ldh = IDIM;
    } else {
        bid -= 640;
        const int bx = bid & 15, by = bid >> 4;
        m0 = by*128; hcol0 = bx*128;
        aptr = x16 + (size_t)(m0 + (tid >> 1))*DIM;
        bptr = B_s + (size_t)(bx*256 + tid)*DIM;
        C = C_s; ldh = SIDIM;
    }

    float acc[4][8][4];
    #pragma unroll
    for (int a = 0; a < 4; a++)
        #pragma unroll
        for (int b = 0; b < 8; b++)
            #pragma unroll
            for (int c = 0; c < 4; c++) acc[a][b][c] = 0.f;

    gemm_mainloop(sb, aptr, bptr, DIM, tid, lane, wm, wn, acc);

    // ---- register-local SwiGLU epilogue: even nt = gate, odd nt = up ----
    #pragma unroll
    for (int mt = 0; mt < 4; mt++)
        #pragma unroll
        for (int p = 0; p < 4; p++) {
            const float* gacc = acc[mt][2*p];
            const float* uacc = acc[mt][2*p + 1];
            const int r = m0 + wm*64 + mt*16 + (lane >> 2);
            const int hc = hcol0 + wn*32 + p*8 + (lane & 3)*2;
            #pragma unroll
            for (int half = 0; half < 2; half++) {
                const float g0 = gacc[half*2],     g1 = gacc[half*2 + 1];
                const float u0 = uacc[half*2],     u1 = uacc[half*2 + 1];
                const float h0 = (g0 / (1.f + expf(-g0))) * u0;
                const float h1 = (g1 / (1.f + expf(-g1))) * u1;
                union { __half b[2]; uint32_t u; } H;
                H.b[0] = __float2half(h0);
                H.b[1] = __float2half(h1);
                *reinterpret_cast<uint32_t*>(C + (long long)(r + half*8)*ldh + hc) = H.u;
            }
        }
}

// ---------- merged down GEMM (fp32 epilogue) ----------
// grid.x = 768: [0,640) routed (8 x, 80 y, K=IDIM), [640,768) shared (8 x, 16 y, K=SIDIM)
__global__ void __launch_bounds__(256, 1) gemm_down_merged(
    const __half* __restrict__ A_r, const __half* __restrict__ B_r,
    float* __restrict__ C_r,
    const __half* __restrict__ A_s, const __half* __restrict__ B_s,
    float* __restrict__ C_s,
    const int* __restrict__ tile_expert)
{
    __shared__ char smem[4*STG];
    const uint32_t sb = smem_to_u32(smem);

    const int tid = threadIdx.x, lane = tid & 31, wid = tid >> 5;
    const int wm = wid & 1, wn = wid >> 1;

    const __half *aptr, *bptr;
    float* C;
    int m0, n0, K;
    int bid = blockIdx.x;
    if (bid < 640) {
        const int bx = bid & 7, by = bid >> 3;
        const int e = tile_expert[by];
        if (e < 0) return;
        m0 = by*128; n0 = bx*256;
        K = IDIM;
        aptr = A_r + (size_t)(m0 + (tid >> 1))*K;
        bptr = B_r + (size_t)(e*DIM + n0 + tid)*K;
        C = C_r;
    } else {
        bid -= 640;
        const int bx = bid & 7, by = bid >> 3;
        m0 = by*128; n0 = bx*256;
        K = SIDIM;
        aptr = A_s + (size_t)(m0 + (tid >> 1))*K;
        bptr = B_s + (size_t)(n0 + tid)*K;
        C = C_s;
    }

    float acc[4][8][4];
    #pragma unroll
    for (int a = 0; a < 4; a++)
        #pragma unroll
        for (int b = 0; b < 8; b++)
            #pragma unroll
            for (int c = 0; c < 4; c++) acc[a][b][c] = 0.f;

    gemm_mainloop(sb, aptr, bptr, K, tid, lane, wm, wn, acc);

    const int rbase = m0 + wm*64 + (lane >> 2);
    const int cbase = n0 + wn*64 + (lane & 3)*2;
    #pragma unroll
    for (int mt = 0; mt < 4; mt++)
        #pragma unroll
        for (int nt = 0; nt < 8; nt++) {
            const long long r0 = rbase + mt*16;
            const int c0 = cbase + nt*8;
            *reinterpret_cast<float2*>(C + r0*DIM + c0) =
                make_float2(acc[mt][nt][0], acc[mt][nt][1]);
            *reinterpret_cast<float2*>(C + (r0+8)*DIM + c0) =
                make_float2(acc[mt][nt][2], acc[mt][nt][3]);
        }
}

// ======================= combine =======================
__global__ void combine_kernel(float* __restrict__ out)
{
    const int t = blockIdx.x;
    __shared__ int   spos[TOPK];
    __shared__ float sw[TOPK];
    if (threadIdx.x < TOPK) {
        spos[threadIdx.x] = g_posmap[t*TOPK + threadIdx.x];
        sw[threadIdx.x]   = g_topw [t*TOPK + threadIdx.x];
    }
    __syncthreads();
    for (int d = threadIdx.x*4; d < DIM; d += blockDim.x*4) {
        float4 a = ld4(out + (long long)t*DIM + d);
        #pragma unroll
        for (int k = 0; k < TOPK; k++) {
            const float4 ev = ld4(g_eout + (long long)spos[k]*DIM + d);
            const float wk = sw[k];
            a.x = fmaf(wk, ev.x, a.x); a.y = fmaf(wk, ev.y, a.y);
            a.z = fmaf(wk, ev.z, a.z); a.w = fmaf(wk, ev.w, a.w);
        }
        *reinterpret_cast<float4*>(out + (long long)t*DIM + d) = a;
    }
}

// ======================= host =======================
extern "C" void kernel_launch(void* const* d_in, const int* in_sizes, int n_in,
                              void* d_out, int out_size)
{
    const float* x    = (const float*)d_in[0];
    const float* gw   = (const float*)d_in[1];
    const float* gb   = (const float*)d_in[2];
    const float* wgu  = (const float*)d_in[3];
    const float* wd   = (const float*)d_in[4];
    const float* wsgu = (const float*)d_in[5];
    const float* wsd  = (const float*)d_in[6];
    float* out = (float*)d_out;

    void *x16, *wguT, *wdT, *wsguT, *wsdT, *hb, *hsh, *eout, *tilee;
    cudaGetSymbolAddress(&x16, g_x16);
    cudaGetSymbolAddress(&wguT, g_wguT);   cudaGetSymbolAddress(&wdT, g_wdT);
    cudaGetSymbolAddress(&wsguT, g_wsguT); cudaGetSymbolAddress(&wsdT, g_wsdT);
    cudaGetSymbolAddress(&hb, g_hb);       cudaGetSymbolAddress(&hsh, g_hsh);
    cudaGetSymbolAddress(&eout, g_eout);
    cudaGetSymbolAddress(&tilee, g_tile_expert);

    // --- routing (+ x conversion fused into router) ---
    zero_meta<<<1, 32>>>();
    router_kernel<<<T_TOK, 512>>>(x, gw, gb, (__half*)x16);
    sched_kernel<<<1, 256>>>();
    scatter_kernel<<<(T_TOK*TOPK + 255)/256, 256>>>();

    // --- weight conversions ---
    transpose_convert<<<dim3(2*IDIM/32, DIM/32, NEXP), dim3(32,8)>>>(
        wgu, (__half*)wguT, DIM, 2*IDIM, IDIM);
    transpose_convert<<<dim3(DIM/32, IDIM/32, NEXP), dim3(32,8)>>>(
        wd, (__half*)wdT, IDIM, DIM, 0);
    transpose_convert<<<dim3(2*SIDIM/32, DIM/32, 1), dim3(32,8)>>>(
        wsgu, (__half*)wsguT, DIM, 2*SIDIM, SIDIM);
    transpose_convert<<<dim3(DIM/32, SIDIM/32, 1), dim3(32,8)>>>(
        wsd, (__half*)wsdT, SIDIM, DIM, 0);

    // --- merged gate_up GEMM + fused gather + SwiGLU (640 routed + 256 shared) ---
    gemm_gu_fused<<<896, 256>>>(
        (const __half*)x16, (const __half*)wguT, (__half*)hb,
        (const __half*)wsguT, (__half*)hsh,
        (const int*)tilee);

    // --- merged down GEMM (640 routed + 128 shared) ---
    gemm_down_merged<<<768, 256>>>(
        (const __half*)hb, (const __half*)wdT, (float*)eout,
        (const __half*)hsh, (const __half*)wsdT, out,
        (const int*)tilee);

    // --- combine ---
    combine_kernel<<<T_TOK, 256>>>(out);
}

// round 16
// speedup vs baseline: 1.1063x; 1.1063x over previous
#include <cuda_runtime.h>
#include <cuda.h>
#include <cuda_fp16.h>
#include <math.h>
#include <stdint.h>

// Problem dims (fixed by setup_inputs)
#define T_TOK 2048
#define DIM   2048
#define NEXP  16
#define IDIM  1024
#define SIDIM 2048
#define TOPK  4

#define BM 128
#define MAXROWS (T_TOK*TOPK + NEXP*BM)   // 10240
#define MAXTILES (MAXROWS/BM)            // 80

// ======================= scratch (device globals) =======================
__device__ __half g_x16[(size_t)T_TOK*DIM];         // x fp16
__device__ __half g_zero[DIM];                      // zero row (static zero-init)
__device__ __half g_wguT[(size_t)NEXP*2*IDIM*DIM];  // pair-interleaved gate/up rows
__device__ __half g_wdT[(size_t)NEXP*DIM*IDIM];
__device__ __half g_wsguT[(size_t)2*SIDIM*DIM];     // pair-interleaved
__device__ __half g_wsdT[(size_t)DIM*SIDIM];
__device__ __half g_hb[(size_t)MAXROWS*IDIM];       // routed hidden fp16
__device__ __half g_hsh[(size_t)T_TOK*SIDIM];       // shared hidden fp16
__device__ float g_eout[(size_t)MAXROWS*DIM];

__device__ int   g_topidx[T_TOK*TOPK];
__device__ float g_topw[T_TOK*TOPK];
__device__ int   g_counts[NEXP];
__device__ int   g_fill[NEXP];
__device__ int   g_offsets[NEXP];
__device__ int   g_tile_expert[MAXTILES];
__device__ int   g_rowtok[MAXROWS];
__device__ int   g_posmap[T_TOK*TOPK];

__device__ __forceinline__ float4 ld4(const float* p) {
    return *reinterpret_cast<const float4*>(p);
}

__device__ __forceinline__ uint32_t smem_to_u32(const void* smem_ptr) {
    uint32_t addr;
    asm("{ .reg .u64 tmp; cvta.to.shared.u64 tmp, %1; cvt.u32.u64 %0, tmp; }"
        : "=r"(addr) : "l"(smem_ptr));
    return addr;
}

// ======================= router (+ fused x fp32->fp16) =======================
__global__ void router_kernel(const float* __restrict__ x,
                              const float* __restrict__ gw,
                              const float* __restrict__ gb,
                              __half* __restrict__ x16)
{
    __shared__ float sx[DIM];
    __shared__ float slog[NEXP];
    const int t   = blockIdx.x;
    const int tid = threadIdx.x;           // 512 threads

    float4 xv0 = ld4(x + (long long)t*DIM + tid*4);
    *reinterpret_cast<float4*>(&sx[tid*4]) = xv0;
    {
        union { __half b[4]; unsigned long long u; } H;
        H.b[0] = __float2half(xv0.x); H.b[1] = __float2half(xv0.y);
        H.b[2] = __float2half(xv0.z); H.b[3] = __float2half(xv0.w);
        *reinterpret_cast<unsigned long long*>(x16 + (long long)t*DIM + tid*4) = H.u;
    }
    __syncthreads();

    const int w = tid >> 5, lane = tid & 31;
    const float* gwr = gw + w*DIM;
    float s = 0.f;
    for (int i = lane*4; i < DIM; i += 32*4) {
        float4 xv = *reinterpret_cast<float4*>(&sx[i]);
        float4 gv = ld4(gwr + i);
        s += xv.x*gv.x + xv.y*gv.y + xv.z*gv.z + xv.w*gv.w;
    }
    #pragma unroll
    for (int o = 16; o; o >>= 1) s += __shfl_down_sync(0xffffffffu, s, o);
    if (lane == 0) slog[w] = s;
    __syncthreads();

    if (tid == 0) {
        float p[NEXP], mx = -1e30f;
        #pragma unroll
        for (int e = 0; e < NEXP; e++) mx = fmaxf(mx, slog[e]);
        float sum = 0.f;
        #pragma unroll
        for (int e = 0; e < NEXP; e++) { p[e] = expf(slog[e] - mx); sum += p[e]; }
        const float inv = 1.f / sum;
        float score[NEXP];
        #pragma unroll
        for (int e = 0; e < NEXP; e++) { p[e] *= inv; score[e] = p[e] + gb[e]; }

        int sel[TOPK]; float wsum = 0.f;
        #pragma unroll
        for (int k = 0; k < TOPK; k++) {
            int best = 0; float bv = -1e30f;
            #pragma unroll
            for (int e = 0; e < NEXP; e++)
                if (score[e] > bv) { bv = score[e]; best = e; }
            sel[k] = best; score[best] = -1e31f; wsum += p[best];
        }
        const float invw = 1.f / wsum;
        #pragma unroll
        for (int k = 0; k < TOPK; k++) {
            g_topidx[t*TOPK + k] = sel[k];
            g_topw [t*TOPK + k] = p[sel[k]] * invw;
            atomicAdd(&g_counts[sel[k]], 1);
        }
    }
}

__global__ void zero_meta()
{
    int i = threadIdx.x;
    if (i < NEXP) { g_counts[i] = 0; g_fill[i] = 0; }
}

__global__ void sched_kernel()
{
    const int tid = threadIdx.x;
    if (tid == 0) {
        int base = 0;
        for (int e = 0; e < NEXP; e++) {
            g_offsets[e] = base;
            int nt = (g_counts[e] + BM - 1) / BM;
            int t0 = base / BM;
            for (int j = 0; j < nt; j++) g_tile_expert[t0 + j] = e;
            base += nt * BM;
        }
        for (int tl = base / BM; tl < MAXTILES; tl++) g_tile_expert[tl] = -1;
    }
    for (int i = tid; i < MAXROWS; i += blockDim.x) g_rowtok[i] = -1;
}

__global__ void scatter_kernel()
{
    const int p = blockIdx.x * blockDim.x + threadIdx.x;
    if (p >= T_TOK*TOPK) return;
    const int e = g_topidx[p];
    const int r = atomicAdd(&g_fill[e], 1);
    const int pos = g_offsets[e] + r;
    g_rowtok[pos] = p >> 2;
    g_posmap[p]   = pos;
}

// ======================= weight conversion =======================
// fp32 src [E][R][C] -> fp16 dst [E][C][R]  (transpose + convert)
// glu_half H != 0: pair-interleave at 8-col granularity —
//   gate col c  -> row (c>>3)*16 + (c&7)
//   up   col c' -> row (c'>>3)*16 + 8 + (c'&7)
// so each n8 mma block pair (even=gate, odd=up) covers the SAME 8 h-columns.
__global__ void transpose_convert(const float* __restrict__ src,
                                  __half* __restrict__ dst,
                                  int R, int C, int glu_half)
{
    __shared__ float t[32][33];
    const int e  = blockIdx.z;
    const int c0 = blockIdx.x * 32;
    const int r0 = blockIdx.y * 32;
    const int tx = threadIdx.x, ty = threadIdx.y;   // (32, 8)
    const float* s = src + (long long)e*R*C;
    #pragma unroll
    for (int j = 0; j < 32; j += 8)
        t[ty+j][tx] = s[(long long)(r0+ty+j)*C + c0+tx];
    __syncthreads();
    __half* o = dst + (long long)e*C*R;
    #pragma unroll
    for (int j = 0; j < 32; j += 8) {
        float v = t[tx][ty+j];
        int c = c0 + ty + j;
        long long dr;
        if (glu_half == 0) dr = c;
        else if (c < glu_half) dr = (long long)(c >> 3)*16 + (c & 7);
        else { int cc = c - glu_half; dr = (long long)(cc >> 3)*16 + 8 + (cc & 7); }
        o[dr*R + r0+tx] = __float2half(v);
    }
}

// ======================= mma.sync GEMM core (fp16, 128x256 tile, 512 thr) =======================
// A [128,K] via per-thread row ptr (tid<256), B [256 rows, K] fp16 K-contig. fp32 accum.
// 512 threads = 16 warps (2 M x 8 N); warp tile 64x32; mma m16n8k16; k-step 16.
// Stage = A 4KB + B 8KB = 12KB (32B rows, swizzle c^((r>>2)&1)); 4 stages = 48KB static.

#define SWZB(r, c)  ((uint32_t)(r)*32u + ((uint32_t)(((c) ^ (((r)>>2)&1))) << 4))
#define B_OFF 4096
#define STG   12288

__device__ __forceinline__ void cp16(uint32_t d, const void* s) {
    asm volatile("cp.async.cg.shared.global [%0], [%1], 16;\n" :: "r"(d), "l"(s));
}
__device__ __forceinline__ void ldm4(uint32_t* r, uint32_t a) {
    asm volatile("ldmatrix.sync.aligned.m8n8.x4.shared.b16 {%0,%1,%2,%3}, [%4];\n"
        : "=r"(r[0]), "=r"(r[1]), "=r"(r[2]), "=r"(r[3]) : "r"(a));
}
__device__ __forceinline__ void mma16816(float* c, const uint32_t* a, uint32_t b0, uint32_t b1) {
    asm volatile("mma.sync.aligned.m16n8k16.row.col.f32.f16.f16.f32 "
        "{%0,%1,%2,%3}, {%4,%5,%6,%7}, {%8,%9}, {%0,%1,%2,%3};\n"
        : "+f"(c[0]), "+f"(c[1]), "+f"(c[2]), "+f"(c[3])
        : "r"(a[0]), "r"(a[1]), "r"(a[2]), "r"(a[3]), "r"(b0), "r"(b1));
}

// aptr: A row (tid>>1) base (valid for tid<256); bptr: B row (tid>>1) base
__device__ __forceinline__ void load_stage(uint32_t st,
    const __half* __restrict__ aptr, const __half* __restrict__ bptr,
    int k0, int tid)
{
    const int row = tid >> 1;          // A: 0..127 (tid<256), B: 0..255
    const int cb  = tid & 1;
    if (tid < 256)
        cp16(st +         SWZB(row, cb), aptr + k0 + cb*8);
    cp16(st + B_OFF + SWZB(row, cb), bptr + k0 + cb*8);
}

__device__ __forceinline__ void gemm_mainloop(uint32_t sb,
    const __half* __restrict__ aptr, const __half* __restrict__ bptr,
    int K, int tid, int lane, int wm, int wn,
    float acc[4][4][4])
{
    const int nk = K / 16;

    load_stage(sb,         aptr, bptr, 0,  tid);
    asm volatile("cp.async.commit_group;\n");
    load_stage(sb + STG,   aptr, bptr, 16, tid);
    asm volatile("cp.async.commit_group;\n");
    load_stage(sb + 2*STG, aptr, bptr, 32, tid);
    asm volatile("cp.async.commit_group;\n");

    for (int kt = 0; kt < nk; kt++) {
        asm volatile("cp.async.wait_group 2;\n");
        __syncthreads();

        if (kt + 3 < nk)
            load_stage(sb + ((kt+3)&3)*STG, aptr, bptr, (kt+3)*16, tid);
        asm volatile("cp.async.commit_group;\n");

        const uint32_t Ab = sb + (kt & 3)*STG;

        // B fragments: 2 x n16k16 per warp (32 B-rows)
        uint32_t fb[2][4];
        #pragma unroll
        for (int np = 0; np < 2; np++) {
            const int rb = wn*32 + np*16 + (lane & 7) + ((lane >> 4) << 3);
            const int cb = (lane >> 3) & 1;
            ldm4(fb[np], Ab + B_OFF + SWZB(rb, cb));
        }

        #pragma unroll
        for (int mt = 0; mt < 4; mt++) {
            uint32_t fa[4];
            const int ra = wm*64 + mt*16 + (lane & 15);
            const int ca = lane >> 4;
            ldm4(fa, Ab + SWZB(ra, ca));
            #pragma unroll
            for (int nt = 0; nt < 4; nt++) {
                const int np = nt >> 1, hx = (nt & 1)*2;
                mma16816(acc[mt][nt], fa, fb[np][hx], fb[np][hx+1]);
            }
        }
    }
    asm volatile("cp.async.wait_group 0;\n");
}

// ---------- merged gate_up GEMM, fused gather + register-local SwiGLU ----------
// grid.x = 896: [0,640) routed (8 x-tiles, 80 y), [640,896) shared (16 x, 16 y)
// B pair-interleaved: n8 block 2q = gate, 2q+1 = up for the SAME 8 h-cols.
__global__ void __launch_bounds__(512, 1) gemm_gu_fused(
    const __half* __restrict__ x16, const __half* __restrict__ B_r,
    __half* __restrict__ C_r,
    const __half* __restrict__ B_s, __half* __restrict__ C_s,
    const int* __restrict__ tile_expert)
{
    __shared__ char smem[4*STG];   // 49152
    const uint32_t sb = smem_to_u32(smem);

    const int tid = threadIdx.x, lane = tid & 31, wid = tid >> 5;
    const int wm = wid & 1, wn = wid >> 1;       // 2 M x 8 N warps

    const __half *aptr, *bptr;
    __half *C;
    int m0, ldh, hcol0;
    int bid = blockIdx.x;
    if (bid < 640) {
        const int bx = bid & 7, by = bid >> 3;
        const int e = tile_expert[by];
        if (e < 0) return;
        m0 = by*128; hcol0 = bx*128;
        const int tok = (tid < 256) ? g_rowtok[m0 + (tid >> 1)] : -1;
        aptr = (tok >= 0) ? (x16 + (size_t)tok*DIM) : g_zero;
        bptr = B_r + (size_t)(e*(2*IDIM) + bx*256 + (tid >> 1))*DIM;
        C = C_r; ldh = IDIM;
    } else {
        bid -= 640;
        const int bx = bid & 15, by = bid >> 4;
        m0 = by*128; hcol0 = bx*128;
        aptr = (tid < 256) ? (x16 + (size_t)(m0 + (tid >> 1))*DIM) : g_zero;
        bptr = B_s + (size_t)(bx*256 + (tid >> 1))*DIM;
        C = C_s; ldh = SIDIM;
    }

    float acc[4][4][4];
    #pragma unroll
    for (int a = 0; a < 4; a++)
        #pragma unroll
        for (int b = 0; b < 4; b++)
            #pragma unroll
            for (int c = 0; c < 4; c++) acc[a][b][c] = 0.f;

    gemm_mainloop(sb, aptr, bptr, DIM, tid, lane, wm, wn, acc);

    // ---- register-local SwiGLU epilogue: even nt = gate, odd nt = up ----
    // Warp covers 32 B rows = 2 (gate,up) pairs = 16 h cols.
    #pragma unroll
    for (int mt = 0; mt < 4; mt++)
        #pragma unroll
        for (int p = 0; p < 2; p++) {
            const float* gacc = acc[mt][2*p];
            const float* uacc = acc[mt][2*p + 1];
            const int r = m0 + wm*64 + mt*16 + (lane >> 2);
            const int hc = hcol0 + wn*16 + p*8 + (lane & 3)*2;
            #pragma unroll
            for (int half = 0; half < 2; half++) {
                const float g0 = gacc[half*2],     g1 = gacc[half*2 + 1];
                const float u0 = uacc[half*2],     u1 = uacc[half*2 + 1];
                const float h0 = (g0 / (1.f + expf(-g0))) * u0;
                const float h1 = (g1 / (1.f + expf(-g1))) * u1;
                union { __half b[2]; uint32_t u; } H;
                H.b[0] = __float2half(h0);
                H.b[1] = __float2half(h1);
                *reinterpret_cast<uint32_t*>(C + (long long)(r + half*8)*ldh + hc) = H.u;
            }
        }
}

// ---------- merged down GEMM (fp32 epilogue) ----------
// grid.x = 768: [0,640) routed (8 x, 80 y, K=IDIM), [640,768) shared (8 x, 16 y, K=SIDIM)
__global__ void __launch_bounds__(512, 1) gemm_down_merged(
    const __half* __restrict__ A_r, const __half* __restrict__ B_r,
    float* __restrict__ C_r,
    const __half* __restrict__ A_s, const __half* __restrict__ B_s,
    float* __restrict__ C_s,
    const int* __restrict__ tile_expert)
{
    __shared__ char smem[4*STG];
    const uint32_t sb = smem_to_u32(smem);

    const int tid = threadIdx.x, lane = tid & 31, wid = tid >> 5;
    const int wm = wid & 1, wn = wid >> 1;       // 2 M x 8 N warps

    const __half *aptr, *bptr;
    float* C;
    int m0, n0, K;
    int bid = blockIdx.x;
    if (bid < 640) {
        const int bx = bid & 7, by = bid >> 3;
        const int e = tile_expert[by];
        if (e < 0) return;
        m0 = by*128; n0 = bx*256;
        K = IDIM;
        aptr = A_r + (size_t)(m0 + ((tid >> 1) & 127))*K;
        bptr = B_r + (size_t)(e*DIM + n0 + (tid >> 1))*K;
        C = C_r;
    } else {
        bid -= 640;
        const int bx = bid & 7, by = bid >> 3;
        m0 = by*128; n0 = bx*256;
        K = SIDIM;
        aptr = A_s + (size_t)(m0 + ((tid >> 1) & 127))*K;
        bptr = B_s + (size_t)(n0 + (tid >> 1))*K;
        C = C_s;
    }

    float acc[4][4][4];
    #pragma unroll
    for (int a = 0; a < 4; a++)
        #pragma unroll
        for (int b = 0; b < 4; b++)
            #pragma unroll
            for (int c = 0; c < 4; c++) acc[a][b][c] = 0.f;

    gemm_mainloop(sb, aptr, bptr, K, tid, lane, wm, wn, acc);

    const int rbase = m0 + wm*64 + (lane >> 2);
    const int cbase = n0 + wn*32 + (lane & 3)*2;
    #pragma unroll
    for (int mt = 0; mt < 4; mt++)
        #pragma unroll
        for (int nt = 0; nt < 4; nt++) {
            const long long r0 = rbase + mt*16;
            const int c0 = cbase + nt*8;
            *reinterpret_cast<float2*>(C + r0*DIM + c0) =
                make_float2(acc[mt][nt][0], acc[mt][nt][1]);
            *reinterpret_cast<float2*>(C + (r0+8)*DIM + c0) =
                make_float2(acc[mt][nt][2], acc[mt][nt][3]);
        }
}

// ======================= combine =======================
__global__ void combine_kernel(float* __restrict__ out)
{
    const int t = blockIdx.x;
    __shared__ int   spos[TOPK];
    __shared__ float sw[TOPK];
    if (threadIdx.x < TOPK) {
        spos[threadIdx.x] = g_posmap[t*TOPK + threadIdx.x];
        sw[threadIdx.x]   = g_topw [t*TOPK + threadIdx.x];
    }
    __syncthreads();
    for (int d = threadIdx.x*4; d < DIM; d += blockDim.x*4) {
        float4 a = ld4(out + (long long)t*DIM + d);
        #pragma unroll
        for (int k = 0; k < TOPK; k++) {
            const float4 ev = ld4(g_eout + (long long)spos[k]*DIM + d);
            const float wk = sw[k];
            a.x = fmaf(wk, ev.x, a.x); a.y = fmaf(wk, ev.y, a.y);
            a.z = fmaf(wk, ev.z, a.z); a.w = fmaf(wk, ev.w, a.w);
        }
        *reinterpret_cast<float4*>(out + (long long)t*DIM + d) = a;
    }
}

// ======================= host =======================
extern "C" void kernel_launch(void* const* d_in, const int* in_sizes, int n_in,
                              void* d_out, int out_size)
{
    const float* x    = (const float*)d_in[0];
    const float* gw   = (const float*)d_in[1];
    const float* gb   = (const float*)d_in[2];
    const float* wgu  = (const float*)d_in[3];
    const float* wd   = (const float*)d_in[4];
    const float* wsgu = (const float*)d_in[5];
    const float* wsd  = (const float*)d_in[6];
    float* out = (float*)d_out;

    void *x16, *wguT, *wdT, *wsguT, *wsdT, *hb, *hsh, *eout, *tilee;
    cudaGetSymbolAddress(&x16, g_x16);
    cudaGetSymbolAddress(&wguT, g_wguT);   cudaGetSymbolAddress(&wdT, g_wdT);
    cudaGetSymbolAddress(&wsguT, g_wsguT); cudaGetSymbolAddress(&wsdT, g_wsdT);
    cudaGetSymbolAddress(&hb, g_hb);       cudaGetSymbolAddress(&hsh, g_hsh);
    cudaGetSymbolAddress(&eout, g_eout);
    cudaGetSymbolAddress(&tilee, g_tile_expert);

    // --- routing (+ x conversion fused into router) ---
    zero_meta<<<1, 32>>>();
    router_kernel<<<T_TOK, 512>>>(x, gw, gb, (__half*)x16);
    sched_kernel<<<1, 256>>>();
    scatter_kernel<<<(T_TOK*TOPK + 255)/256, 256>>>();

    // --- weight conversions ---
    transpose_convert<<<dim3(2*IDIM/32, DIM/32, NEXP), dim3(32,8)>>>(
        wgu, (__half*)wguT, DIM, 2*IDIM, IDIM);
    transpose_convert<<<dim3(DIM/32, IDIM/32, NEXP), dim3(32,8)>>>(
        wd, (__half*)wdT, IDIM, DIM, 0);
    transpose_convert<<<dim3(2*SIDIM/32, DIM/32, 1), dim3(32,8)>>>(
        wsgu, (__half*)wsguT, DIM, 2*SIDIM, SIDIM);
    transpose_convert<<<dim3(DIM/32, SIDIM/32, 1), dim3(32,8)>>>(
        wsd, (__half*)wsdT, SIDIM, DIM, 0);

    // --- merged gate_up GEMM + fused gather + SwiGLU (640 routed + 256 shared) ---
    gemm_gu_fused<<<896, 512>>>(
        (const __half*)x16, (const __half*)wguT, (__half*)hb,
        (const __half*)wsguT, (__half*)hsh,
        (const int*)tilee);

    // --- merged down GEMM (640 routed + 128 shared) ---
    gemm_down_merged<<<768, 512>>>(
        (const __half*)hb, (const __half*)wdT, (float*)eout,
        (const __half*)hsh, (const __half*)wsdT, out,
        (const int*)tilee);

    // --- combine ---
    combine_kernel<<<T_TOK, 256>>>(out);
}

// round 17
// speedup vs baseline: 1.2165x; 1.0996x over previous
#include <cuda_runtime.h>
#include <cuda.h>
#include <cuda_fp16.h>
#include <math.h>
#include <stdint.h>

// Problem dims (fixed by setup_inputs)
#define T_TOK 2048
#define DIM   2048
#define NEXP  16
#define IDIM  1024
#define SIDIM 2048
#define TOPK  4

#define BM 128
#define MAXROWS (T_TOK*TOPK + NEXP*BM)   // 10240
#define MAXTILES (MAXROWS/BM)            // 80

// ======================= scratch (device globals) =======================
__device__ __half g_x16[(size_t)T_TOK*DIM];         // x fp16
__device__ __half g_zero[DIM];                      // zero row (static zero-init)
__device__ __half g_wguT[(size_t)NEXP*2*IDIM*DIM];  // pair-interleaved gate/up rows
__device__ __half g_wdT[(size_t)NEXP*DIM*IDIM];
__device__ __half g_wsguT[(size_t)2*SIDIM*DIM];     // pair-interleaved
__device__ __half g_wsdT[(size_t)DIM*SIDIM];
__device__ __half g_hb[(size_t)MAXROWS*IDIM];       // routed hidden fp16
__device__ __half g_hsh[(size_t)T_TOK*SIDIM];       // shared hidden fp16
__device__ __half g_eout[(size_t)MAXROWS*DIM];      // routed expert out (fp16)

__device__ int   g_topidx[T_TOK*TOPK];
__device__ float g_topw[T_TOK*TOPK];
__device__ int   g_counts[NEXP];
__device__ int   g_fill[NEXP];
__device__ int   g_offsets[NEXP];
__device__ int   g_tile_expert[MAXTILES];
__device__ int   g_rowtok[MAXROWS];
__device__ int   g_posmap[T_TOK*TOPK];

__device__ __forceinline__ float4 ld4(const float* p) {
    return *reinterpret_cast<const float4*>(p);
}

__device__ __forceinline__ uint32_t smem_to_u32(const void* smem_ptr) {
    uint32_t addr;
    asm("{ .reg .u64 tmp; cvta.to.shared.u64 tmp, %1; cvt.u32.u64 %0, tmp; }"
        : "=r"(addr) : "l"(smem_ptr));
    return addr;
}

// ======================= router (+ fused x fp32->fp16) =======================
__global__ void router_kernel(const float* __restrict__ x,
                              const float* __restrict__ gw,
                              const float* __restrict__ gb,
                              __half* __restrict__ x16)
{
    __shared__ float sx[DIM];
    __shared__ float slog[NEXP];
    const int t   = blockIdx.x;
    const int tid = threadIdx.x;           // 512 threads

    float4 xv0 = ld4(x + (long long)t*DIM + tid*4);
    *reinterpret_cast<float4*>(&sx[tid*4]) = xv0;
    {
        union { __half b[4]; unsigned long long u; } H;
        H.b[0] = __float2half(xv0.x); H.b[1] = __float2half(xv0.y);
        H.b[2] = __float2half(xv0.z); H.b[3] = __float2half(xv0.w);
        *reinterpret_cast<unsigned long long*>(x16 + (long long)t*DIM + tid*4) = H.u;
    }
    __syncthreads();

    const int w = tid >> 5, lane = tid & 31;
    const float* gwr = gw + w*DIM;
    float s = 0.f;
    for (int i = lane*4; i < DIM; i += 32*4) {
        float4 xv = *reinterpret_cast<float4*>(&sx[i]);
        float4 gv = ld4(gwr + i);
        s += xv.x*gv.x + xv.y*gv.y + xv.z*gv.z + xv.w*gv.w;
    }
    #pragma unroll
    for (int o = 16; o; o >>= 1) s += __shfl_down_sync(0xffffffffu, s, o);
    if (lane == 0) slog[w] = s;
    __syncthreads();

    if (tid == 0) {
        float p[NEXP], mx = -1e30f;
        #pragma unroll
        for (int e = 0; e < NEXP; e++) mx = fmaxf(mx, slog[e]);
        float sum = 0.f;
        #pragma unroll
        for (int e = 0; e < NEXP; e++) { p[e] = expf(slog[e] - mx); sum += p[e]; }
        const float inv = 1.f / sum;
        float score[NEXP];
        #pragma unroll
        for (int e = 0; e < NEXP; e++) { p[e] *= inv; score[e] = p[e] + gb[e]; }

        int sel[TOPK]; float wsum = 0.f;
        #pragma unroll
        for (int k = 0; k < TOPK; k++) {
            int best = 0; float bv = -1e30f;
            #pragma unroll
            for (int e = 0; e < NEXP; e++)
                if (score[e] > bv) { bv = score[e]; best = e; }
            sel[k] = best; score[best] = -1e31f; wsum += p[best];
        }
        const float invw = 1.f / wsum;
        #pragma unroll
        for (int k = 0; k < TOPK; k++) {
            g_topidx[t*TOPK + k] = sel[k];
            g_topw [t*TOPK + k] = p[sel[k]] * invw;
            atomicAdd(&g_counts[sel[k]], 1);
        }
    }
}

__global__ void zero_meta()
{
    int i = threadIdx.x;
    if (i < NEXP) { g_counts[i] = 0; g_fill[i] = 0; }
}

__global__ void sched_kernel()
{
    const int tid = threadIdx.x;
    if (tid == 0) {
        int base = 0;
        for (int e = 0; e < NEXP; e++) {
            g_offsets[e] = base;
            int nt = (g_counts[e] + BM - 1) / BM;
            int t0 = base / BM;
            for (int j = 0; j < nt; j++) g_tile_expert[t0 + j] = e;
            base += nt * BM;
        }
        for (int tl = base / BM; tl < MAXTILES; tl++) g_tile_expert[tl] = -1;
    }
    for (int i = tid; i < MAXROWS; i += blockDim.x) g_rowtok[i] = -1;
}

__global__ void scatter_kernel()
{
    const int p = blockIdx.x * blockDim.x + threadIdx.x;
    if (p >= T_TOK*TOPK) return;
    const int e = g_topidx[p];
    const int r = atomicAdd(&g_fill[e], 1);
    const int pos = g_offsets[e] + r;
    g_rowtok[pos] = p >> 2;
    g_posmap[p]   = pos;
}

// ======================= weight conversion =======================
// fp32 src [E][R][C] -> fp16 dst [E][C][R]  (transpose + convert)
// glu_half H != 0: pair-interleave at 8-col granularity —
//   gate col c  -> row (c>>3)*16 + (c&7)
//   up   col c' -> row (c'>>3)*16 + 8 + (c'&7)
// so each n8 mma block pair (even=gate, odd=up) covers the SAME 8 h-columns.
__global__ void transpose_convert(const float* __restrict__ src,
                                  __half* __restrict__ dst,
                                  int R, int C, int glu_half)
{
    __shared__ float t[32][33];
    const int e  = blockIdx.z;
    const int c0 = blockIdx.x * 32;
    const int r0 = blockIdx.y * 32;
    const int tx = threadIdx.x, ty = threadIdx.y;   // (32, 8)
    const float* s = src + (long long)e*R*C;
    #pragma unroll
    for (int j = 0; j < 32; j += 8)
        t[ty+j][tx] = s[(long long)(r0+ty+j)*C + c0+tx];
    __syncthreads();
    __half* o = dst + (long long)e*C*R;
    #pragma unroll
    for (int j = 0; j < 32; j += 8) {
        float v = t[tx][ty+j];
        int c = c0 + ty + j;
        long long dr;
        if (glu_half == 0) dr = c;
        else if (c < glu_half) dr = (long long)(c >> 3)*16 + (c & 7);
        else { int cc = c - glu_half; dr = (long long)(cc >> 3)*16 + 8 + (cc & 7); }
        o[dr*R + r0+tx] = __float2half(v);
    }
}

// ======================= mma.sync GEMM core (fp16, k-step 32, 4 stages) =======================
// C tile 128x128. A via per-thread row pointer, B [N,K] fp16 K-contig. fp32 accum.
// 256 threads = 8 warps (2 M x 4 N); warp tile 64x32; mma m16n8k16.
// Stage = A 8KB + B 8KB = 16KB (64B rows, 4x16B chunks = k 0..31,
// swizzle c^((r>>1)&3)); 4 stages = 64KB dynamic smem, occ 2.

#define SWZ64(r, c) ((uint32_t)(r)*64u + ((uint32_t)(((c) ^ (((r)>>1)&3))) << 4))
#define B_OFF 8192
#define STG   16384
#define GSMEM (4*STG)   // 65536

__device__ __forceinline__ void cp16(uint32_t d, const void* s) {
    asm volatile("cp.async.cg.shared.global [%0], [%1], 16;\n" :: "r"(d), "l"(s));
}
__device__ __forceinline__ void ldm4(uint32_t* r, uint32_t a) {
    asm volatile("ldmatrix.sync.aligned.m8n8.x4.shared.b16 {%0,%1,%2,%3}, [%4];\n"
        : "=r"(r[0]), "=r"(r[1]), "=r"(r[2]), "=r"(r[3]) : "r"(a));
}
__device__ __forceinline__ void mma16816(float* c, const uint32_t* a, uint32_t b0, uint32_t b1) {
    asm volatile("mma.sync.aligned.m16n8k16.row.col.f32.f16.f16.f32 "
        "{%0,%1,%2,%3}, {%4,%5,%6,%7}, {%8,%9}, {%0,%1,%2,%3};\n"
        : "+f"(c[0]), "+f"(c[1]), "+f"(c[2]), "+f"(c[3])
        : "r"(a[0]), "r"(a[1]), "r"(a[2]), "r"(a[3]), "r"(b0), "r"(b1));
}

// aptr/bptr: this thread's A/B row base pointers (row = tid>>1)
__device__ __forceinline__ void load_stage(uint32_t st,
    const __half* __restrict__ aptr, const __half* __restrict__ bptr,
    int k0, int tid)
{
    const int row = tid >> 1;
    const int c0  = (tid & 1) * 2;    // chunks c0, c0+1
    cp16(st +         SWZ64(row, c0),     aptr + k0 + c0*8);
    cp16(st +         SWZ64(row, c0 + 1), aptr + k0 + c0*8 + 8);
    cp16(st + B_OFF + SWZ64(row, c0),     bptr + k0 + c0*8);
    cp16(st + B_OFF + SWZ64(row, c0 + 1), bptr + k0 + c0*8 + 8);
}

__device__ __forceinline__ void gemm_mainloop(uint32_t sb,
    const __half* __restrict__ aptr, const __half* __restrict__ bptr,
    int K, int tid, int lane, int wm, int wn,
    float acc[4][4][4])
{
    const int nk = K / 32;   // >= 32 always

    load_stage(sb,         aptr, bptr, 0,  tid);
    asm volatile("cp.async.commit_group;\n");
    load_stage(sb + STG,   aptr, bptr, 32, tid);
    asm volatile("cp.async.commit_group;\n");
    load_stage(sb + 2*STG, aptr, bptr, 64, tid);
    asm volatile("cp.async.commit_group;\n");

    for (int kt = 0; kt < nk; kt++) {
        asm volatile("cp.async.wait_group 2;\n");
        __syncthreads();

        if (kt + 3 < nk)
            load_stage(sb + ((kt+3)&3)*STG, aptr, bptr, (kt+3)*32, tid);
        asm volatile("cp.async.commit_group;\n");

        const uint32_t Ab = sb + (kt & 3)*STG;

        #pragma unroll
        for (int kh = 0; kh < 2; kh++) {
            uint32_t fb[2][4];
            #pragma unroll
            for (int np = 0; np < 2; np++) {
                const int rb = wn*32 + np*16 + (lane & 7) + ((lane >> 4) << 3);
                const int cb = kh*2 + ((lane >> 3) & 1);
                ldm4(fb[np], Ab + B_OFF + SWZ64(rb, cb));
            }
            #pragma unroll
            for (int mt = 0; mt < 4; mt++) {
                uint32_t fa[4];
                const int ra = wm*64 + mt*16 + (lane & 15);
                const int ca = kh*2 + (lane >> 4);
                ldm4(fa, Ab + SWZ64(ra, ca));
                #pragma unroll
                for (int nt = 0; nt < 4; nt++) {
                    const int np = nt >> 1, hx = (nt & 1)*2;
                    mma16816(acc[mt][nt], fa, fb[np][hx], fb[np][hx+1]);
                }
            }
        }
    }
    asm volatile("cp.async.wait_group 0;\n");
}

// ---------- merged gate_up GEMM, fused gather + register-local SwiGLU ----------
// grid.x = 1792: [0,1280) routed (16 x-tiles, 80 y), [1280,1792) shared (32 x, 16 y)
// B pair-interleaved (16-row granularity): warp's 32 B rows = 2 (gate8,up8) pairs
// covering h cols [wn*16, wn*16+16) of this tile's 64 h-columns.
__global__ void __launch_bounds__(256, 2) gemm_gu_fused(
    const __half* __restrict__ x16, const __half* __restrict__ B_r,
    __half* __restrict__ C_r,
    const __half* __restrict__ B_s, __half* __restrict__ C_s,
    const int* __restrict__ tile_expert)
{
    extern __shared__ char smem[];
    const uint32_t sb = smem_to_u32(smem);

    const int tid = threadIdx.x, lane = tid & 31, wid = tid >> 5;
    const int wm = wid & 1, wn = wid >> 1;
    const int row = tid >> 1;

    const __half *aptr, *bptr;
    __half *C;
    int m0, ldh, hcol0;
    int bid = blockIdx.x;
    if (bid < 1280) {
        const int bx = bid & 15, by = bid >> 4;
        const int e = tile_expert[by];
        if (e < 0) return;
        m0 = by*128; hcol0 = bx*64;
        const int brow0 = e*(2*IDIM) + bx*128;
        const int tok = g_rowtok[m0 + row];
        aptr = (tok >= 0) ? (x16 + (size_t)tok*DIM) : g_zero;
        bptr = B_r + (size_t)(brow0 + row)*DIM;
        C = C_r; ldh = IDIM;
    } else {
        bid -= 1280;
        const int bx = bid & 31, by = bid >> 5;
        m0 = by*128; hcol0 = bx*64;
        aptr = x16 + (size_t)(m0 + row)*DIM;
        bptr = B_s + (size_t)(bx*128 + row)*DIM;
        C = C_s; ldh = SIDIM;
    }

    float acc[4][4][4];
    #pragma unroll
    for (int a = 0; a < 4; a++)
        #pragma unroll
        for (int b = 0; b < 4; b++)
            #pragma unroll
            for (int c = 0; c < 4; c++) acc[a][b][c] = 0.f;

    gemm_mainloop(sb, aptr, bptr, DIM, tid, lane, wm, wn, acc);

    // ---- register-local SwiGLU epilogue: even nt = gate, odd nt = up ----
    #pragma unroll
    for (int mt = 0; mt < 4; mt++)
        #pragma unroll
        for (int p = 0; p < 2; p++) {
            const float* gacc = acc[mt][2*p];
            const float* uacc = acc[mt][2*p + 1];
            const int r = m0 + wm*64 + mt*16 + (lane >> 2);
            const int hc = hcol0 + wn*16 + p*8 + (lane & 3)*2;
            #pragma unroll
            for (int half = 0; half < 2; half++) {
                const float g0 = gacc[half*2],     g1 = gacc[half*2 + 1];
                const float u0 = uacc[half*2],     u1 = uacc[half*2 + 1];
                const float h0 = (g0 / (1.f + expf(-g0))) * u0;
                const float h1 = (g1 / (1.f + expf(-g1))) * u1;
                union { __half b[2]; uint32_t u; } H;
                H.b[0] = __float2half(h0);
                H.b[1] = __float2half(h1);
                *reinterpret_cast<uint32_t*>(C + (long long)(r + half*8)*ldh + hc) = H.u;
            }
        }
}

// ---------- merged down GEMM ----------
// grid.x = 1536: [0,1280) routed (16 x, 80 y, K=IDIM) -> fp16 eout,
//                [1280,1536) shared (16 x, 16 y, K=SIDIM) -> fp32 out
__global__ void __launch_bounds__(256, 2) gemm_down_merged(
    const __half* __restrict__ A_r, const __half* __restrict__ B_r,
    __half* __restrict__ C_r,
    const __half* __restrict__ A_s, const __half* __restrict__ B_s,
    float* __restrict__ C_s,
    const int* __restrict__ tile_expert)
{
    extern __shared__ char smem[];
    const uint32_t sb = smem_to_u32(smem);

    const int tid = threadIdx.x, lane = tid & 31, wid = tid >> 5;
    const int wm = wid & 1, wn = wid >> 1;
    const int row = tid >> 1;

    const __half *aptr, *bptr;
    int m0, n0, K;
    bool routed;
    int bid = blockIdx.x;
    if (bid < 1280) {
        const int bx = bid & 15, by = bid >> 4;
        const int e = tile_expert[by];
        if (e < 0) return;
        m0 = by*128; n0 = bx*128;
        K = IDIM;
        aptr = A_r + (size_t)(m0 + row)*K;
        bptr = B_r + (size_t)(e*DIM + n0 + row)*K;
        routed = true;
    } else {
        bid -= 1280;
        const int bx = bid & 15, by = bid >> 4;
        m0 = by*128; n0 = bx*128;
        K = SIDIM;
        aptr = A_s + (size_t)(m0 + row)*K;
        bptr = B_s + (size_t)(n0 + row)*K;
        routed = false;
    }

    float acc[4][4][4];
    #pragma unroll
    for (int a = 0; a < 4; a++)
        #pragma unroll
        for (int b = 0; b < 4; b++)
            #pragma unroll
            for (int c = 0; c < 4; c++) acc[a][b][c] = 0.f;

    gemm_mainloop(sb, aptr, bptr, K, tid, lane, wm, wn, acc);

    const int rbase = m0 + wm*64 + (lane >> 2);
    const int cbase = n0 + wn*32 + (lane & 3)*2;
    if (routed) {
        #pragma unroll
        for (int mt = 0; mt < 4; mt++)
            #pragma unroll
            for (int nt = 0; nt < 4; nt++) {
                const long long r0 = rbase + mt*16;
                const int c0 = cbase + nt*8;
                union { __half b[2]; uint32_t u; } H0, H1;
                H0.b[0] = __float2half(acc[mt][nt][0]);
                H0.b[1] = __float2half(acc[mt][nt][1]);
                H1.b[0] = __float2half(acc[mt][nt][2]);
                H1.b[1] = __float2half(acc[mt][nt][3]);
                *reinterpret_cast<uint32_t*>(C_r + r0*DIM + c0)     = H0.u;
                *reinterpret_cast<uint32_t*>(C_r + (r0+8)*DIM + c0) = H1.u;
            }
    } else {
        #pragma unroll
        for (int mt = 0; mt < 4; mt++)
            #pragma unroll
            for (int nt = 0; nt < 4; nt++) {
                const long long r0 = rbase + mt*16;
                const int c0 = cbase + nt*8;
                *reinterpret_cast<float2*>(C_s + r0*DIM + c0) =
                    make_float2(acc[mt][nt][0], acc[mt][nt][1]);
                *reinterpret_cast<float2*>(C_s + (r0+8)*DIM + c0) =
                    make_float2(acc[mt][nt][2], acc[mt][nt][3]);
            }
    }
}

// ======================= combine =======================
__global__ void combine_kernel(float* __restrict__ out)
{
    const int t = blockIdx.x;
    __shared__ int   spos[TOPK];
    __shared__ float sw[TOPK];
    if (threadIdx.x < TOPK) {
        spos[threadIdx.x] = g_posmap[t*TOPK + threadIdx.x];
        sw[threadIdx.x]   = g_topw [t*TOPK + threadIdx.x];
    }
    __syncthreads();
    for (int d = threadIdx.x*4; d < DIM; d += blockDim.x*4) {
        float4 a = ld4(out + (long long)t*DIM + d);
        #pragma unroll
        for (int k = 0; k < TOPK; k++) {
            const __half2* e2 = reinterpret_cast<const __half2*>(
                g_eout + (long long)spos[k]*DIM + d);
            const float2 lo = __half22float2(e2[0]);
            const float2 hi = __half22float2(e2[1]);
            const float wk = sw[k];
            a.x = fmaf(wk, lo.x, a.x); a.y = fmaf(wk, lo.y, a.y);
            a.z = fmaf(wk, hi.x, a.z); a.w = fmaf(wk, hi.y, a.w);
        }
        *reinterpret_cast<float4*>(out + (long long)t*DIM + d) = a;
    }
}

// ======================= host =======================
extern "C" void kernel_launch(void* const* d_in, const int* in_sizes, int n_in,
                              void* d_out, int out_size)
{
    const float* x    = (const float*)d_in[0];
    const float* gw   = (const float*)d_in[1];
    const float* gb   = (const float*)d_in[2];
    const float* wgu  = (const float*)d_in[3];
    const float* wd   = (const float*)d_in[4];
    const float* wsgu = (const float*)d_in[5];
    const float* wsd  = (const float*)d_in[6];
    float* out = (float*)d_out;

    void *x16, *wguT, *wdT, *wsguT, *wsdT, *hb, *hsh, *eout, *tilee;
    cudaGetSymbolAddress(&x16, g_x16);
    cudaGetSymbolAddress(&wguT, g_wguT);   cudaGetSymbolAddress(&wdT, g_wdT);
    cudaGetSymbolAddress(&wsguT, g_wsguT); cudaGetSymbolAddress(&wsdT, g_wsdT);
    cudaGetSymbolAddress(&hb, g_hb);       cudaGetSymbolAddress(&hsh, g_hsh);
    cudaGetSymbolAddress(&eout, g_eout);
    cudaGetSymbolAddress(&tilee, g_tile_expert);

    cudaFuncSetAttribute(gemm_gu_fused,
                         cudaFuncAttributeMaxDynamicSharedMemorySize, GSMEM);
    cudaFuncSetAttribute(gemm_down_merged,
                         cudaFuncAttributeMaxDynamicSharedMemorySize, GSMEM);

    // --- routing (+ x conversion fused into router) ---
    zero_meta<<<1, 32>>>();
    router_kernel<<<T_TOK, 512>>>(x, gw, gb, (__half*)x16);
    sched_kernel<<<1, 256>>>();
    scatter_kernel<<<(T_TOK*TOPK + 255)/256, 256>>>();

    // --- weight conversions ---
    transpose_convert<<<dim3(2*IDIM/32, DIM/32, NEXP), dim3(32,8)>>>(
        wgu, (__half*)wguT, DIM, 2*IDIM, IDIM);
    transpose_convert<<<dim3(DIM/32, IDIM/32, NEXP), dim3(32,8)>>>(
        wd, (__half*)wdT, IDIM, DIM, 0);
    transpose_convert<<<dim3(2*SIDIM/32, DIM/32, 1), dim3(32,8)>>>(
        wsgu, (__half*)wsguT, DIM, 2*SIDIM, SIDIM);
    transpose_convert<<<dim3(DIM/32, SIDIM/32, 1), dim3(32,8)>>>(
        wsd, (__half*)wsdT, SIDIM, DIM, 0);

    // --- merged gate_up GEMM + fused gather + SwiGLU (1280 routed + 512 shared) ---
    gemm_gu_fused<<<1792, 256, GSMEM>>>(
        (const __half*)x16, (const __half*)wguT, (__half*)hb,
        (const __half*)wsguT, (__half*)hsh,
        (const int*)tilee);

    // --- merged down GEMM (1280 routed -> fp16 eout, 256 shared -> fp32 out) ---
    gemm_down_merged<<<1536, 256, GSMEM>>>(
        (const __half*)hb, (const __half*)wdT, (__half*)eout,
        (const __half*)hsh, (const __half*)wsdT, out,
        (const int*)tilee);

    // --- combine ---
    combine_kernel<<<T_TOK, 256>>>(out);
}